// round 15
// baseline (speedup 1.0000x reference)
#include <cuda_runtime.h>
#include <cuda_fp16.h>
#include <math.h>
#include <stdint.h>

// Problem shapes (fixed)
#define NTOK 16384
#define CDIM 256
#define HDIM 682
#define HPAD 704            // 11 chunks of 64
#define NEXP 8
#define TM   128            // block M tile (slots)
#define BK   64
#define PADDED_MAX (NTOK*2 + NEXP*TM)   // 33792
#define MTILES (PADDED_MAX / TM)        // 264
#define WPELEM (NEXP * HPAD * CDIM)     // 1441792
#define ROUTER_BLOCKS (NTOK / 8)        // 2048
#define PREP_BLOCKS   ((WPELEM / 4 + 255) / 256)  // 1408

// ---------------- device scratch (zero-initialized at load) --------------
__device__ int    d_counts[NEXP];        // 0 at load; re-zeroed by k_setup each run
__device__ int    d_poff[NEXP + 1];
__device__ int    d_cursor[NEXP];
__device__ int    d_slot_token[PADDED_MAX];
__device__ int    d_tok_slot[NTOK * 2];
__device__ float  d_tok_gate[NTOK * 2];
__device__ int    d_tok_expert[NTOK * 2];
__device__ __half d_h[(size_t)PADDED_MAX * HPAD];
__device__ __half d_yvh[(size_t)PADDED_MAX * CDIM];   // fp16 expert outputs
// fp16 operand copies
__device__ __half d_xc[(size_t)NTOK * CDIM];
__device__ __half d_w1c[WPELEM];   // [E][HPAD][CDIM]
__device__ __half d_w3c[WPELEM];   // [E][HPAD][CDIM]
__device__ __half d_w2c[WPELEM];   // [E][CDIM][HPAD]

// ---------------- helpers ----------------
__device__ __forceinline__ uint32_t smem_u32(const void* p) {
    uint32_t a;
    asm("{ .reg .u64 t; cvta.to.shared.u64 t, %1; cvt.u32.u64 %0, t; }" : "=r"(a) : "l"(p));
    return a;
}
__device__ __forceinline__ void mma_fp16(float c[4], uint32_t a0, uint32_t a1,
                                         uint32_t a2, uint32_t a3,
                                         uint32_t b0, uint32_t b1) {
    asm volatile(
        "mma.sync.aligned.m16n8k16.row.col.f32.f16.f16.f32 "
        "{%0,%1,%2,%3}, {%4,%5,%6,%7}, {%8,%9}, {%0,%1,%2,%3};"
        : "+f"(c[0]), "+f"(c[1]), "+f"(c[2]), "+f"(c[3])
        : "r"(a0), "r"(a1), "r"(a2), "r"(a3), "r"(b0), "r"(b1));
}
__device__ __forceinline__ void cp16(uint32_t dst, const void* src, uint32_t bytes) {
    asm volatile("cp.async.cg.shared.global [%0], [%1], 16, %2;"
                 :: "r"(dst), "l"(src), "r"(bytes) : "memory");
}
#define CP_COMMIT() asm volatile("cp.async.commit_group;" ::: "memory")
#define CP_WAIT(n)  asm volatile("cp.async.wait_group %0;" :: "n"(n) : "memory")

// SMEM offsets in HALF units, pitch 72 halves (144B) -> conflict-free, 2 stages
#define PITCH 72
#define G1_A(st)  ((st) * 9216)
#define G1_B1(st) (18432 + (st) * 4608)
#define G1_B3(st) (27648 + (st) * 4608)
#define G1_BYTES  73728
#define G2_A(st)  ((st) * 9216)
#define G2_B(st)  (18432 + (st) * 9216)
#define G2_BYTES  73728

// ------- k_front: merged router (blocks 0..2047) + prep (rest) -----------
__global__ void __launch_bounds__(256) k_front(const float* __restrict__ x,
                                               const float* __restrict__ rw,
                                               const float* __restrict__ w1,
                                               const float* __restrict__ w3,
                                               const float* __restrict__ w2) {
    if (blockIdx.x < ROUTER_BLOCKS) {
        // ---- router ----
        __shared__ float s_rw[NEXP * CDIM];
        for (int i = threadIdx.x; i < NEXP * CDIM; i += blockDim.x) s_rw[i] = rw[i];
        __syncthreads();
        int warp = threadIdx.x >> 5, lane = threadIdx.x & 31;
        int n = blockIdx.x * 8 + warp;
        if (n >= NTOK) return;
        const float* xr = x + (size_t)n * CDIM;
        float acc[NEXP];
#pragma unroll
        for (int e = 0; e < NEXP; e++) acc[e] = 0.f;
        for (int c = lane; c < CDIM; c += 32) {
            float xv = xr[c];
            d_xc[(size_t)n * CDIM + c] = __float2half_rn(xv);
#pragma unroll
            for (int e = 0; e < NEXP; e++) acc[e] = fmaf(xv, s_rw[e * CDIM + c], acc[e]);
        }
#pragma unroll
        for (int e = 0; e < NEXP; e++)
#pragma unroll
            for (int off = 16; off; off >>= 1)
                acc[e] += __shfl_down_sync(0xffffffffu, acc[e], off);
        if (lane != 0) return;
        float m = acc[0];
#pragma unroll
        for (int e = 1; e < NEXP; e++) m = fmaxf(m, acc[e]);
        float p[NEXP], s = 0.f;
#pragma unroll
        for (int e = 0; e < NEXP; e++) { p[e] = expf(acc[e] - m); s += p[e]; }
        float inv = 1.f / s;
#pragma unroll
        for (int e = 0; e < NEXP; e++) p[e] *= inv;
        int i0 = 0;
#pragma unroll
        for (int e = 1; e < NEXP; e++) if (p[e] > p[i0]) i0 = e;
        int i1 = (i0 == 0) ? 1 : 0;
#pragma unroll
        for (int e = 0; e < NEXP; e++) if (e != i0 && p[e] > p[i1]) i1 = e;
        float denom = p[i0] + p[i1] + 1e-9f;
        d_tok_expert[2 * n + 0] = i0;
        d_tok_expert[2 * n + 1] = i1;
        d_tok_gate[2 * n + 0] = p[i0] / denom;
        d_tok_gate[2 * n + 1] = p[i1] / denom;
        atomicAdd(&d_counts[i0], 1);
        atomicAdd(&d_counts[i1], 1);
    } else {
        // ---- prep: slot init + weight convert/pad (NO d_counts writes) ----
        int i = (blockIdx.x - ROUTER_BLOCKS) * blockDim.x + threadIdx.x;
        if (i < PADDED_MAX) d_slot_token[i] = -1;
        if (i >= WPELEM / 4) return;

        {   // w1/w3 -> half [E][HPAD][CDIM]
            int c4 = i & 63;
            int h  = (i >> 6) % HPAD;
            int e  = i / (64 * HPAD);
            float4 a = make_float4(0.f, 0.f, 0.f, 0.f), b = a;
            if (h < HDIM) {
                size_t off = ((size_t)e * HDIM + h) * CDIM + c4 * 4;
                a = *(const float4*)(w1 + off);
                b = *(const float4*)(w3 + off);
            }
            __half2* p1 = (__half2*)&d_w1c[(size_t)i * 4];
            __half2* p3 = (__half2*)&d_w3c[(size_t)i * 4];
            p1[0] = __floats2half2_rn(a.x, a.y); p1[1] = __floats2half2_rn(a.z, a.w);
            p3[0] = __floats2half2_rn(b.x, b.y); p3[1] = __floats2half2_rn(b.z, b.w);
        }
        {   // w2 -> half [E][CDIM][HPAD]
            int h4 = (i % 176) * 4;
            int c  = (i / 176) % CDIM;
            int e  = i / (176 * CDIM);
            const float* src = w2 + ((size_t)e * CDIM + c) * HDIM + h4;
            float4 v = make_float4(0.f, 0.f, 0.f, 0.f);
            if (h4 + 3 < HDIM) { v.x = src[0]; v.y = src[1]; v.z = src[2]; v.w = src[3]; }
            else {
                if (h4 + 0 < HDIM) v.x = src[0];
                if (h4 + 1 < HDIM) v.y = src[1];
            }
            __half2* p2 = (__half2*)&d_w2c[(size_t)i * 4];
            p2[0] = __floats2half2_rn(v.x, v.y); p2[1] = __floats2half2_rn(v.z, v.w);
        }
    }
}

// setup: consume counts -> padded offsets, then re-zero counts.
__global__ void k_setup() {
    if (threadIdx.x == 0) {
        int off = 0;
        for (int e = 0; e < NEXP; e++) {
            d_poff[e] = off;
            d_cursor[e] = off;
            off += ((d_counts[e] + TM - 1) / TM) * TM;
            d_counts[e] = 0;
        }
        d_poff[NEXP] = off;
    }
}

__global__ void k_scatter() {
    int i = blockIdx.x * blockDim.x + threadIdx.x;
    if (i >= NTOK * 2) return;
    int n = i >> 1;
    int e = d_tok_expert[i];
    int pos = atomicAdd(&d_cursor[e], 1);
    d_slot_token[pos] = n;
    d_tok_slot[i] = pos;
}

// ---------------- GEMM1: h = silu(x w1^T) * (x w3^T) ---------------------
// 128 thr = 4 warps (2M x 2N), warp tile 64x32, block 128x64, BK=64, 2-stage.
// minctasm=3 caps regs at 170 -> 3 CTAs/SM with 73.7KB smem.
__global__ void __launch_bounds__(128, 3) k_gemm1_mma() {
    extern __shared__ __half smh[];
    __shared__ int s_tok[TM];
    uint32_t sb = smem_u32(smh);

    int sbase = blockIdx.x * TM;
    if (sbase >= d_poff[NEXP]) return;
    int e = 0;
#pragma unroll
    for (int q = 0; q < NEXP - 1; q++) if (d_poff[q + 1] <= sbase) e = q + 1;
    int n0 = blockIdx.y * 64;

    int tid = threadIdx.x, lane = tid & 31, wid = tid >> 5;
    int wm = wid >> 1, wn = wid & 1;
    s_tok[tid] = d_slot_token[sbase + tid];
    __syncthreads();

    const __half* w1e = d_w1c + (size_t)e * HPAD * CDIM;
    const __half* w3e = d_w3c + (size_t)e * HPAD * CDIM;

    auto load_chunk = [&](int c, int st) {
        int k0 = c * BK;
#pragma unroll
        for (int t = 0; t < 8; t++) {                    // A: 1024 x 16B
            int i = tid + t * 128;
            int m = i >> 3, f4 = i & 7;
            int tok = s_tok[m];
            const __half* src = (tok >= 0) ? &d_xc[(size_t)tok * CDIM + k0 + f4 * 8] : d_xc;
            cp16(sb + (G1_A(st) + m * PITCH + f4 * 8) * 2, src, (tok >= 0) ? 16u : 0u);
        }
#pragma unroll
        for (int t = 0; t < 4; t++) {                    // B1/B3: 512 x 16B each
            int i = tid + t * 128;
            int nn = i >> 3, f4 = i & 7;
            size_t off = (size_t)(n0 + nn) * CDIM + k0 + f4 * 8;
            cp16(sb + (G1_B1(st) + nn * PITCH + f4 * 8) * 2, w1e + off, 16u);
            cp16(sb + (G1_B3(st) + nn * PITCH + f4 * 8) * 2, w3e + off, 16u);
        }
    };

    float c1[4][4][4], c3[4][4][4];
#pragma unroll
    for (int mt = 0; mt < 4; mt++)
#pragma unroll
        for (int nt = 0; nt < 4; nt++)
#pragma unroll
            for (int r = 0; r < 4; r++) { c1[mt][nt][r] = 0.f; c3[mt][nt][r] = 0.f; }

    int lr = lane >> 2, lc = lane & 3;
    const int NC = CDIM / BK;   // 4

    load_chunk(0, 0);
    CP_COMMIT();

    for (int c = 0; c < NC; c++) {
        int st = c & 1;
        if (c + 1 < NC) { load_chunk(c + 1, st ^ 1); CP_COMMIT(); CP_WAIT(1); }
        else            { CP_WAIT(0); }
        __syncthreads();

        const __half* As  = smh + G1_A(st);
        const __half* B1s = smh + G1_B1(st);
        const __half* B3s = smh + G1_B3(st);
#pragma unroll
        for (int ks = 0; ks < BK / 16; ks++) {
            int k = ks * 16;
            uint32_t a[4][4];
#pragma unroll
            for (int mt = 0; mt < 4; mt++) {
                int row = wm * 64 + mt * 16 + lr;
                a[mt][0] = *(const uint32_t*)&As[row * PITCH + k + lc * 2];
                a[mt][1] = *(const uint32_t*)&As[(row + 8) * PITCH + k + lc * 2];
                a[mt][2] = *(const uint32_t*)&As[row * PITCH + k + 8 + lc * 2];
                a[mt][3] = *(const uint32_t*)&As[(row + 8) * PITCH + k + 8 + lc * 2];
            }
#pragma unroll
            for (int nt = 0; nt < 4; nt++) {
                int col = wn * 32 + nt * 8 + lr;
                uint32_t b10 = *(const uint32_t*)&B1s[col * PITCH + k + lc * 2];
                uint32_t b11 = *(const uint32_t*)&B1s[col * PITCH + k + 8 + lc * 2];
                uint32_t b30 = *(const uint32_t*)&B3s[col * PITCH + k + lc * 2];
                uint32_t b31 = *(const uint32_t*)&B3s[col * PITCH + k + 8 + lc * 2];
#pragma unroll
                for (int mt = 0; mt < 4; mt++) {
                    mma_fp16(c1[mt][nt], a[mt][0], a[mt][1], a[mt][2], a[mt][3], b10, b11);
                    mma_fp16(c3[mt][nt], a[mt][0], a[mt][1], a[mt][2], a[mt][3], b30, b31);
                }
            }
        }
        __syncthreads();
    }

    // epilogue: h = silu(c1)*c3 -> half
#pragma unroll
    for (int mt = 0; mt < 4; mt++) {
#pragma unroll
        for (int nt = 0; nt < 4; nt++) {
#pragma unroll
            for (int half = 0; half < 2; half++) {
                int row = sbase + wm * 64 + mt * 16 + lr + half * 8;
                int col = n0 + wn * 32 + nt * 8 + lc * 2;
                float a0 = c1[mt][nt][half * 2 + 0], a1 = c1[mt][nt][half * 2 + 1];
                float b0 = c3[mt][nt][half * 2 + 0], b1 = c3[mt][nt][half * 2 + 1];
                float h0 = a0 / (1.f + expf(-a0)) * b0;
                float h1 = a1 / (1.f + expf(-a1)) * b1;
                *(__half2*)&d_h[(size_t)row * HPAD + col] = __floats2half2_rn(h0, h1);
            }
        }
    }
}

// ---------------- GEMM2: y = h w2^T (fp16 output) ------------------------
// 128 thr = 4 warps (2M x 2N), warp tile 64x64, block 128x128, BK=64, 2-stage.
__global__ void __launch_bounds__(128, 3) k_gemm2_mma() {
    extern __shared__ __half smh[];
    uint32_t sb = smem_u32(smh);

    int sbase = blockIdx.x * TM;
    if (sbase >= d_poff[NEXP]) return;
    int e = 0;
#pragma unroll
    for (int q = 0; q < NEXP - 1; q++) if (d_poff[q + 1] <= sbase) e = q + 1;
    int n0 = blockIdx.y * 128;

    int tid = threadIdx.x, lane = tid & 31, wid = tid >> 5;
    int wm = wid >> 1, wn = wid & 1;
    const __half* w2e = d_w2c + (size_t)e * CDIM * HPAD;

    auto load_chunk = [&](int c, int st) {
        int k0 = c * BK;
#pragma unroll
        for (int t = 0; t < 8; t++) {                    // A (d_h): 1024 x 16B
            int i = tid + t * 128;
            int m = i >> 3, f4 = i & 7;
            cp16(sb + (G2_A(st) + m * PITCH + f4 * 8) * 2,
                 &d_h[(size_t)(sbase + m) * HPAD + k0 + f4 * 8], 16u);
        }
#pragma unroll
        for (int t = 0; t < 8; t++) {                    // B (w2c): 1024 x 16B
            int i = tid + t * 128;
            int nn = i >> 3, f4 = i & 7;
            cp16(sb + (G2_B(st) + nn * PITCH + f4 * 8) * 2,
                 &w2e[(size_t)(n0 + nn) * HPAD + k0 + f4 * 8], 16u);
        }
    };

    float cacc[4][8][4];
#pragma unroll
    for (int mt = 0; mt < 4; mt++)
#pragma unroll
        for (int nt = 0; nt < 8; nt++)
#pragma unroll
            for (int r = 0; r < 4; r++) cacc[mt][nt][r] = 0.f;

    int lr = lane >> 2, lc = lane & 3;
    const int NC = HPAD / BK;   // 11

    load_chunk(0, 0);
    CP_COMMIT();

    for (int c = 0; c < NC; c++) {
        int st = c & 1;
        if (c + 1 < NC) { load_chunk(c + 1, st ^ 1); CP_COMMIT(); CP_WAIT(1); }
        else            { CP_WAIT(0); }
        __syncthreads();

        const __half* As = smh + G2_A(st);
        const __half* Bs = smh + G2_B(st);
#pragma unroll
        for (int ks = 0; ks < BK / 16; ks++) {
            int k = ks * 16;
            uint32_t a[4][4];
#pragma unroll
            for (int mt = 0; mt < 4; mt++) {
                int row = wm * 64 + mt * 16 + lr;
                a[mt][0] = *(const uint32_t*)&As[row * PITCH + k + lc * 2];
                a[mt][1] = *(const uint32_t*)&As[(row + 8) * PITCH + k + lc * 2];
                a[mt][2] = *(const uint32_t*)&As[row * PITCH + k + 8 + lc * 2];
                a[mt][3] = *(const uint32_t*)&As[(row + 8) * PITCH + k + 8 + lc * 2];
            }
#pragma unroll
            for (int nt = 0; nt < 8; nt++) {
                int col = wn * 64 + nt * 8 + lr;
                uint32_t b0 = *(const uint32_t*)&Bs[col * PITCH + k + lc * 2];
                uint32_t b1 = *(const uint32_t*)&Bs[col * PITCH + k + 8 + lc * 2];
#pragma unroll
                for (int mt = 0; mt < 4; mt++)
                    mma_fp16(cacc[mt][nt], a[mt][0], a[mt][1], a[mt][2], a[mt][3], b0, b1);
            }
        }
        __syncthreads();
    }

#pragma unroll
    for (int mt = 0; mt < 4; mt++) {
#pragma unroll
        for (int nt = 0; nt < 8; nt++) {
#pragma unroll
            for (int half = 0; half < 2; half++) {
                int row = sbase + wm * 64 + mt * 16 + lr + half * 8;
                int col = n0 + wn * 64 + nt * 8 + lc * 2;
                *(__half2*)&d_yvh[(size_t)row * CDIM + col] =
                    __floats2half2_rn(cacc[mt][nt][half * 2 + 0],
                                      cacc[mt][nt][half * 2 + 1]);
            }
        }
    }
}

// ---------------- combine (reads fp16 y) ----------------
__global__ void k_combine(float* __restrict__ out) {
    int idx = blockIdx.x * blockDim.x + threadIdx.x;
    if (idx >= NTOK * (CDIM / 4)) return;
    int n = idx >> 6, c4 = idx & 63;
    int s0 = d_tok_slot[2 * n + 0], s1 = d_tok_slot[2 * n + 1];
    float g0 = d_tok_gate[2 * n + 0], g1 = d_tok_gate[2 * n + 1];
    __half2 y0a = *(const __half2*)&d_yvh[(size_t)s0 * CDIM + c4 * 4];
    __half2 y0b = *(const __half2*)&d_yvh[(size_t)s0 * CDIM + c4 * 4 + 2];
    __half2 y1a = *(const __half2*)&d_yvh[(size_t)s1 * CDIM + c4 * 4];
    __half2 y1b = *(const __half2*)&d_yvh[(size_t)s1 * CDIM + c4 * 4 + 2];
    float2 f0a = __half22float2(y0a), f0b = __half22float2(y0b);
    float2 f1a = __half22float2(y1a), f1b = __half22float2(y1b);
    float4 o;
    o.x = g0 * f0a.x + g1 * f1a.x;
    o.y = g0 * f0a.y + g1 * f1a.y;
    o.z = g0 * f0b.x + g1 * f1b.x;
    o.w = g0 * f0b.y + g1 * f1b.y;
    *(float4*)&out[(size_t)n * CDIM + c4 * 4] = o;
}

// ---------------- launch ----------------
extern "C" void kernel_launch(void* const* d_in, const int* in_sizes, int n_in,
                              void* d_out, int out_size) {
    const float* x  = (const float*)d_in[0];
    const float* rw = (const float*)d_in[1];
    const float* w1 = (const float*)d_in[2];
    const float* w2 = (const float*)d_in[3];
    const float* w3 = (const float*)d_in[4];
    float* out = (float*)d_out;

    cudaFuncSetAttribute(k_gemm1_mma, cudaFuncAttributeMaxDynamicSharedMemorySize, G1_BYTES);
    cudaFuncSetAttribute(k_gemm2_mma, cudaFuncAttributeMaxDynamicSharedMemorySize, G2_BYTES);

    k_front<<<ROUTER_BLOCKS + PREP_BLOCKS, 256>>>(x, rw, w1, w3, w2);
    k_setup<<<1, 32>>>();
    k_scatter<<<(NTOK * 2 + 255) / 256, 256>>>();

    dim3 g1(MTILES, HPAD / 64);              // 264 x 11
    k_gemm1_mma<<<g1, 128, G1_BYTES>>>();

    dim3 g2(MTILES, CDIM / 128);             // 264 x 2
    k_gemm2_mma<<<g2, 128, G2_BYTES>>>();

    k_combine<<<(NTOK * (CDIM / 4) + 255) / 256, 256>>>(out);
}

// round 16
// speedup vs baseline: 1.0756x; 1.0756x over previous
#include <cuda_runtime.h>
#include <cuda_fp16.h>
#include <math.h>
#include <stdint.h>

// Problem shapes (fixed)
#define NTOK 16384
#define CDIM 256
#define HDIM 682
#define HPAD 704            // 11 chunks of 64
#define NEXP 8
#define TM   128            // block M tile (slots)
#define BK   64
#define PADDED_MAX (NTOK*2 + NEXP*TM)   // 33792
#define MTILES (PADDED_MAX / TM)        // 264
#define WPELEM (NEXP * HPAD * CDIM)     // 1441792
#define ROUTER_BLOCKS (NTOK / 8)        // 2048
#define PREP_BLOCKS   ((WPELEM / 4 + 255) / 256)  // 1408

// ---------------- device scratch (zero-initialized at load) --------------
__device__ int    d_counts[NEXP];
__device__ int    d_poff[NEXP + 1];
__device__ int    d_cursor[NEXP];
__device__ int    d_slot_token[PADDED_MAX];
__device__ int    d_tok_slot[NTOK * 2];
__device__ float  d_tok_gate[NTOK * 2];
__device__ int    d_tok_expert[NTOK * 2];
__device__ __half d_h[(size_t)PADDED_MAX * HPAD];
__device__ __half d_yvh[(size_t)PADDED_MAX * CDIM];
// fp16 operand copies
__device__ __half d_xc[(size_t)NTOK * CDIM];
__device__ __half d_w1c[WPELEM];   // [E][HPAD][CDIM]
__device__ __half d_w3c[WPELEM];   // [E][HPAD][CDIM]
__device__ __half d_w2c[WPELEM];   // [E][CDIM][HPAD]

// ---------------- helpers ----------------
__device__ __forceinline__ uint32_t smem_u32(const void* p) {
    uint32_t a;
    asm("{ .reg .u64 t; cvta.to.shared.u64 t, %1; cvt.u32.u64 %0, t; }" : "=r"(a) : "l"(p));
    return a;
}
__device__ __forceinline__ void mma_fp16(float c[4], uint32_t a0, uint32_t a1,
                                         uint32_t a2, uint32_t a3,
                                         uint32_t b0, uint32_t b1) {
    asm volatile(
        "mma.sync.aligned.m16n8k16.row.col.f32.f16.f16.f32 "
        "{%0,%1,%2,%3}, {%4,%5,%6,%7}, {%8,%9}, {%0,%1,%2,%3};"
        : "+f"(c[0]), "+f"(c[1]), "+f"(c[2]), "+f"(c[3])
        : "r"(a0), "r"(a1), "r"(a2), "r"(a3), "r"(b0), "r"(b1));
}
__device__ __forceinline__ void ldsm4(uint32_t& r0, uint32_t& r1, uint32_t& r2,
                                      uint32_t& r3, uint32_t addr) {
    asm volatile("ldmatrix.sync.aligned.m8n8.x4.shared.b16 {%0,%1,%2,%3}, [%4];"
                 : "=r"(r0), "=r"(r1), "=r"(r2), "=r"(r3) : "r"(addr));
}
__device__ __forceinline__ void cp16(uint32_t dst, const void* src, uint32_t bytes) {
    asm volatile("cp.async.cg.shared.global [%0], [%1], 16, %2;"
                 :: "r"(dst), "l"(src), "r"(bytes) : "memory");
}
#define CP_COMMIT() asm volatile("cp.async.commit_group;" ::: "memory")
#define CP_WAIT(n)  asm volatile("cp.async.wait_group %0;" :: "n"(n) : "memory")

// SMEM offsets in HALF units, pitch 72 halves (144B) -> conflict-free, 2 stages
#define PITCH 72
#define G1_A(st)  ((st) * 9216)
#define G1_B1(st) (18432 + (st) * 4608)
#define G1_B3(st) (27648 + (st) * 4608)
#define G1_BYTES  73728
#define G2_A(st)  ((st) * 9216)
#define G2_B(st)  (18432 + (st) * 9216)
#define G2_BYTES  73728

// ------- k_front: merged router (blocks 0..2047) + prep (rest) -----------
__global__ void __launch_bounds__(256) k_front(const float* __restrict__ x,
                                               const float* __restrict__ rw,
                                               const float* __restrict__ w1,
                                               const float* __restrict__ w3,
                                               const float* __restrict__ w2) {
    if (blockIdx.x < ROUTER_BLOCKS) {
        // ---- router (vectorized x path) ----
        __shared__ float s_rw[NEXP * CDIM];
        for (int i = threadIdx.x; i < NEXP * CDIM; i += blockDim.x) s_rw[i] = rw[i];
        __syncthreads();
        int warp = threadIdx.x >> 5, lane = threadIdx.x & 31;
        int n = blockIdx.x * 8 + warp;
        if (n >= NTOK) return;
        const float* xr = x + (size_t)n * CDIM;
        float acc[NEXP];
#pragma unroll
        for (int e = 0; e < NEXP; e++) acc[e] = 0.f;
#pragma unroll
        for (int ch = 0; ch < 2; ch++) {
            int c = ch * 128 + lane * 4;
            float4 v = *(const float4*)&xr[c];
            __half2* dst = (__half2*)&d_xc[(size_t)n * CDIM + c];
            dst[0] = __floats2half2_rn(v.x, v.y);
            dst[1] = __floats2half2_rn(v.z, v.w);
#pragma unroll
            for (int e = 0; e < NEXP; e++) {
                acc[e] = fmaf(v.x, s_rw[e * CDIM + c + 0], acc[e]);
                acc[e] = fmaf(v.y, s_rw[e * CDIM + c + 1], acc[e]);
                acc[e] = fmaf(v.z, s_rw[e * CDIM + c + 2], acc[e]);
                acc[e] = fmaf(v.w, s_rw[e * CDIM + c + 3], acc[e]);
            }
        }
#pragma unroll
        for (int e = 0; e < NEXP; e++)
#pragma unroll
            for (int off = 16; off; off >>= 1)
                acc[e] += __shfl_down_sync(0xffffffffu, acc[e], off);
        if (lane != 0) return;
        float m = acc[0];
#pragma unroll
        for (int e = 1; e < NEXP; e++) m = fmaxf(m, acc[e]);
        float p[NEXP], s = 0.f;
#pragma unroll
        for (int e = 0; e < NEXP; e++) { p[e] = expf(acc[e] - m); s += p[e]; }
        float inv = 1.f / s;
#pragma unroll
        for (int e = 0; e < NEXP; e++) p[e] *= inv;
        int i0 = 0;
#pragma unroll
        for (int e = 1; e < NEXP; e++) if (p[e] > p[i0]) i0 = e;
        int i1 = (i0 == 0) ? 1 : 0;
#pragma unroll
        for (int e = 0; e < NEXP; e++) if (e != i0 && p[e] > p[i1]) i1 = e;
        float denom = p[i0] + p[i1] + 1e-9f;
        d_tok_expert[2 * n + 0] = i0;
        d_tok_expert[2 * n + 1] = i1;
        d_tok_gate[2 * n + 0] = p[i0] / denom;
        d_tok_gate[2 * n + 1] = p[i1] / denom;
        atomicAdd(&d_counts[i0], 1);
        atomicAdd(&d_counts[i1], 1);
    } else {
        // ---- prep: slot init + weight convert/pad (NO d_counts writes) ----
        int i = (blockIdx.x - ROUTER_BLOCKS) * blockDim.x + threadIdx.x;
        if (i < PADDED_MAX) d_slot_token[i] = -1;
        if (i >= WPELEM / 4) return;

        {   // w1/w3 -> half [E][HPAD][CDIM]
            int c4 = i & 63;
            int h  = (i >> 6) % HPAD;
            int e  = i / (64 * HPAD);
            float4 a = make_float4(0.f, 0.f, 0.f, 0.f), b = a;
            if (h < HDIM) {
                size_t off = ((size_t)e * HDIM + h) * CDIM + c4 * 4;
                a = *(const float4*)(w1 + off);
                b = *(const float4*)(w3 + off);
            }
            __half2* p1 = (__half2*)&d_w1c[(size_t)i * 4];
            __half2* p3 = (__half2*)&d_w3c[(size_t)i * 4];
            p1[0] = __floats2half2_rn(a.x, a.y); p1[1] = __floats2half2_rn(a.z, a.w);
            p3[0] = __floats2half2_rn(b.x, b.y); p3[1] = __floats2half2_rn(b.z, b.w);
        }
        {   // w2 -> half [E][CDIM][HPAD]
            int h4 = (i % 176) * 4;
            int c  = (i / 176) % CDIM;
            int e  = i / (176 * CDIM);
            const float* src = w2 + ((size_t)e * CDIM + c) * HDIM + h4;
            float4 v = make_float4(0.f, 0.f, 0.f, 0.f);
            if (h4 + 3 < HDIM) { v.x = src[0]; v.y = src[1]; v.z = src[2]; v.w = src[3]; }
            else {
                if (h4 + 0 < HDIM) v.x = src[0];
                if (h4 + 1 < HDIM) v.y = src[1];
            }
            __half2* p2 = (__half2*)&d_w2c[(size_t)i * 4];
            p2[0] = __floats2half2_rn(v.x, v.y); p2[1] = __floats2half2_rn(v.z, v.w);
        }
    }
}

__global__ void k_setup() {
    if (threadIdx.x == 0) {
        int off = 0;
        for (int e = 0; e < NEXP; e++) {
            d_poff[e] = off;
            d_cursor[e] = off;
            off += ((d_counts[e] + TM - 1) / TM) * TM;
            d_counts[e] = 0;
        }
        d_poff[NEXP] = off;
    }
}

__global__ void k_scatter() {
    int i = blockIdx.x * blockDim.x + threadIdx.x;
    if (i >= NTOK * 2) return;
    int n = i >> 1;
    int e = d_tok_expert[i];
    int pos = atomicAdd(&d_cursor[e], 1);
    d_slot_token[pos] = n;
    d_tok_slot[i] = pos;
}

// ---------------- GEMM1: h = silu(x w1^T) * (x w3^T) ---------------------
// 128 thr = 4 warps (2M x 2N), warp tile 64x32, block 128x64, BK=64,
// 2-stage, ldmatrix fragments, minctasm=3.
__global__ void __launch_bounds__(128, 3) k_gemm1_mma() {
    extern __shared__ __half smh[];
    __shared__ int s_tok[TM];
    uint32_t sb = smem_u32(smh);

    int sbase = blockIdx.x * TM;
    if (sbase >= d_poff[NEXP]) return;
    int e = 0;
#pragma unroll
    for (int q = 0; q < NEXP - 1; q++) if (d_poff[q + 1] <= sbase) e = q + 1;
    int n0 = blockIdx.y * 64;

    int tid = threadIdx.x, lane = tid & 31, wid = tid >> 5;
    int wm = wid >> 1, wn = wid & 1;
    s_tok[tid] = d_slot_token[sbase + tid];
    __syncthreads();

    const __half* w1e = d_w1c + (size_t)e * HPAD * CDIM;
    const __half* w3e = d_w3c + (size_t)e * HPAD * CDIM;

    auto load_chunk = [&](int c, int st) {
        int k0 = c * BK;
#pragma unroll
        for (int t = 0; t < 8; t++) {                    // A: 1024 x 16B
            int i = tid + t * 128;
            int m = i >> 3, f4 = i & 7;
            int tok = s_tok[m];
            const __half* src = (tok >= 0) ? &d_xc[(size_t)tok * CDIM + k0 + f4 * 8] : d_xc;
            cp16(sb + (G1_A(st) + m * PITCH + f4 * 8) * 2, src, (tok >= 0) ? 16u : 0u);
        }
#pragma unroll
        for (int t = 0; t < 4; t++) {                    // B1/B3: 512 x 16B each
            int i = tid + t * 128;
            int nn = i >> 3, f4 = i & 7;
            size_t off = (size_t)(n0 + nn) * CDIM + k0 + f4 * 8;
            cp16(sb + (G1_B1(st) + nn * PITCH + f4 * 8) * 2, w1e + off, 16u);
            cp16(sb + (G1_B3(st) + nn * PITCH + f4 * 8) * 2, w3e + off, 16u);
        }
    };

    float c1[4][4][4], c3[4][4][4];
#pragma unroll
    for (int mt = 0; mt < 4; mt++)
#pragma unroll
        for (int nt = 0; nt < 4; nt++)
#pragma unroll
            for (int r = 0; r < 4; r++) { c1[mt][nt][r] = 0.f; c3[mt][nt][r] = 0.f; }

    int lr = lane >> 2, lc = lane & 3;
    // ldmatrix lane addressing (validated in R9's passing run)
    int arow = (lane & 7) + ((lane >> 3) & 1) * 8;   // A row within 16
    int akof = ((lane >> 4) & 1) * 8;                // A k offset
    int brow = ((lane >> 4) & 1) * 8 + (lane & 7);   // B row (n) within 16
    int bkof = ((lane >> 3) & 1) * 8;                // B k offset
    const int NC = CDIM / BK;   // 4

    load_chunk(0, 0);
    CP_COMMIT();

    for (int c = 0; c < NC; c++) {
        int st = c & 1;
        if (c + 1 < NC) { load_chunk(c + 1, st ^ 1); CP_COMMIT(); CP_WAIT(1); }
        else            { CP_WAIT(0); }
        __syncthreads();

#pragma unroll
        for (int ks = 0; ks < BK / 16; ks++) {
            int k = ks * 16;
            uint32_t a[4][4], b1r[4][2], b3r[4][2];
#pragma unroll
            for (int mt = 0; mt < 4; mt++) {
                int row = wm * 64 + mt * 16 + arow;
                ldsm4(a[mt][0], a[mt][1], a[mt][2], a[mt][3],
                      sb + (G1_A(st) + row * PITCH + k + akof) * 2);
            }
#pragma unroll
            for (int p = 0; p < 2; p++) {
                int col = wn * 32 + p * 16 + brow;
                ldsm4(b1r[p*2][0], b1r[p*2][1], b1r[p*2+1][0], b1r[p*2+1][1],
                      sb + (G1_B1(st) + col * PITCH + k + bkof) * 2);
                ldsm4(b3r[p*2][0], b3r[p*2][1], b3r[p*2+1][0], b3r[p*2+1][1],
                      sb + (G1_B3(st) + col * PITCH + k + bkof) * 2);
            }
#pragma unroll
            for (int nt = 0; nt < 4; nt++)
#pragma unroll
                for (int mt = 0; mt < 4; mt++) {
                    mma_fp16(c1[mt][nt], a[mt][0], a[mt][1], a[mt][2], a[mt][3],
                             b1r[nt][0], b1r[nt][1]);
                    mma_fp16(c3[mt][nt], a[mt][0], a[mt][1], a[mt][2], a[mt][3],
                             b3r[nt][0], b3r[nt][1]);
                }
        }
        __syncthreads();
    }

    // epilogue: h = silu(c1)*c3 -> half
#pragma unroll
    for (int mt = 0; mt < 4; mt++) {
#pragma unroll
        for (int nt = 0; nt < 4; nt++) {
#pragma unroll
            for (int half = 0; half < 2; half++) {
                int row = sbase + wm * 64 + mt * 16 + lr + half * 8;
                int col = n0 + wn * 32 + nt * 8 + lc * 2;
                float a0 = c1[mt][nt][half * 2 + 0], a1 = c1[mt][nt][half * 2 + 1];
                float b0 = c3[mt][nt][half * 2 + 0], b1 = c3[mt][nt][half * 2 + 1];
                float h0 = a0 / (1.f + expf(-a0)) * b0;
                float h1 = a1 / (1.f + expf(-a1)) * b1;
                *(__half2*)&d_h[(size_t)row * HPAD + col] = __floats2half2_rn(h0, h1);
            }
        }
    }
}

// ---------------- GEMM2: y = h w2^T (fp16 output) ------------------------
// 128 thr = 4 warps (2M x 2N), warp tile 64x64, block 128x128, BK=64,
// 2-stage, ldmatrix fragments, minctasm=3.
__global__ void __launch_bounds__(128, 3) k_gemm2_mma() {
    extern __shared__ __half smh[];
    uint32_t sb = smem_u32(smh);

    int sbase = blockIdx.x * TM;
    if (sbase >= d_poff[NEXP]) return;
    int e = 0;
#pragma unroll
    for (int q = 0; q < NEXP - 1; q++) if (d_poff[q + 1] <= sbase) e = q + 1;
    int n0 = blockIdx.y * 128;

    int tid = threadIdx.x, lane = tid & 31, wid = tid >> 5;
    int wm = wid >> 1, wn = wid & 1;
    const __half* w2e = d_w2c + (size_t)e * CDIM * HPAD;

    auto load_chunk = [&](int c, int st) {
        int k0 = c * BK;
#pragma unroll
        for (int t = 0; t < 8; t++) {                    // A (d_h): 1024 x 16B
            int i = tid + t * 128;
            int m = i >> 3, f4 = i & 7;
            cp16(sb + (G2_A(st) + m * PITCH + f4 * 8) * 2,
                 &d_h[(size_t)(sbase + m) * HPAD + k0 + f4 * 8], 16u);
        }
#pragma unroll
        for (int t = 0; t < 8; t++) {                    // B (w2c): 1024 x 16B
            int i = tid + t * 128;
            int nn = i >> 3, f4 = i & 7;
            cp16(sb + (G2_B(st) + nn * PITCH + f4 * 8) * 2,
                 &w2e[(size_t)(n0 + nn) * HPAD + k0 + f4 * 8], 16u);
        }
    };

    float cacc[4][8][4];
#pragma unroll
    for (int mt = 0; mt < 4; mt++)
#pragma unroll
        for (int nt = 0; nt < 8; nt++)
#pragma unroll
            for (int r = 0; r < 4; r++) cacc[mt][nt][r] = 0.f;

    int lr = lane >> 2, lc = lane & 3;
    int arow = (lane & 7) + ((lane >> 3) & 1) * 8;
    int akof = ((lane >> 4) & 1) * 8;
    int brow = ((lane >> 4) & 1) * 8 + (lane & 7);
    int bkof = ((lane >> 3) & 1) * 8;
    const int NC = HPAD / BK;   // 11

    load_chunk(0, 0);
    CP_COMMIT();

    for (int c = 0; c < NC; c++) {
        int st = c & 1;
        if (c + 1 < NC) { load_chunk(c + 1, st ^ 1); CP_COMMIT(); CP_WAIT(1); }
        else            { CP_WAIT(0); }
        __syncthreads();

#pragma unroll
        for (int ks = 0; ks < BK / 16; ks++) {
            int k = ks * 16;
            uint32_t a[4][4], br[8][2];
#pragma unroll
            for (int mt = 0; mt < 4; mt++) {
                int row = wm * 64 + mt * 16 + arow;
                ldsm4(a[mt][0], a[mt][1], a[mt][2], a[mt][3],
                      sb + (G2_A(st) + row * PITCH + k + akof) * 2);
            }
#pragma unroll
            for (int p = 0; p < 4; p++) {
                int col = wn * 64 + p * 16 + brow;
                ldsm4(br[p*2][0], br[p*2][1], br[p*2+1][0], br[p*2+1][1],
                      sb + (G2_B(st) + col * PITCH + k + bkof) * 2);
            }
#pragma unroll
            for (int nt = 0; nt < 8; nt++)
#pragma unroll
                for (int mt = 0; mt < 4; mt++)
                    mma_fp16(cacc[mt][nt], a[mt][0], a[mt][1], a[mt][2], a[mt][3],
                             br[nt][0], br[nt][1]);
        }
        __syncthreads();
    }

#pragma unroll
    for (int mt = 0; mt < 4; mt++) {
#pragma unroll
        for (int nt = 0; nt < 8; nt++) {
#pragma unroll
            for (int half = 0; half < 2; half++) {
                int row = sbase + wm * 64 + mt * 16 + lr + half * 8;
                int col = n0 + wn * 64 + nt * 8 + lc * 2;
                *(__half2*)&d_yvh[(size_t)row * CDIM + col] =
                    __floats2half2_rn(cacc[mt][nt][half * 2 + 0],
                                      cacc[mt][nt][half * 2 + 1]);
            }
        }
    }
}

// ---------------- combine (reads fp16 y) ----------------
__global__ void k_combine(float* __restrict__ out) {
    int idx = blockIdx.x * blockDim.x + threadIdx.x;
    if (idx >= NTOK * (CDIM / 4)) return;
    int n = idx >> 6, c4 = idx & 63;
    int s0 = d_tok_slot[2 * n + 0], s1 = d_tok_slot[2 * n + 1];
    float g0 = d_tok_gate[2 * n + 0], g1 = d_tok_gate[2 * n + 1];
    __half2 y0a = *(const __half2*)&d_yvh[(size_t)s0 * CDIM + c4 * 4];
    __half2 y0b = *(const __half2*)&d_yvh[(size_t)s0 * CDIM + c4 * 4 + 2];
    __half2 y1a = *(const __half2*)&d_yvh[(size_t)s1 * CDIM + c4 * 4];
    __half2 y1b = *(const __half2*)&d_yvh[(size_t)s1 * CDIM + c4 * 4 + 2];
    float2 f0a = __half22float2(y0a), f0b = __half22float2(y0b);
    float2 f1a = __half22float2(y1a), f1b = __half22float2(y1b);
    float4 o;
    o.x = g0 * f0a.x + g1 * f1a.x;
    o.y = g0 * f0a.y + g1 * f1a.y;
    o.z = g0 * f0b.x + g1 * f1b.x;
    o.w = g0 * f0b.y + g1 * f1b.y;
    *(float4*)&out[(size_t)n * CDIM + c4 * 4] = o;
}

// ---------------- launch ----------------
extern "C" void kernel_launch(void* const* d_in, const int* in_sizes, int n_in,
                              void* d_out, int out_size) {
    const float* x  = (const float*)d_in[0];
    const float* rw = (const float*)d_in[1];
    const float* w1 = (const float*)d_in[2];
    const float* w2 = (const float*)d_in[3];
    const float* w3 = (const float*)d_in[4];
    float* out = (float*)d_out;

    cudaFuncSetAttribute(k_gemm1_mma, cudaFuncAttributeMaxDynamicSharedMemorySize, G1_BYTES);
    cudaFuncSetAttribute(k_gemm2_mma, cudaFuncAttributeMaxDynamicSharedMemorySize, G2_BYTES);

    k_front<<<ROUTER_BLOCKS + PREP_BLOCKS, 256>>>(x, rw, w1, w3, w2);
    k_setup<<<1, 32>>>();
    k_scatter<<<(NTOK * 2 + 255) / 256, 256>>>();

    dim3 g1(MTILES, HPAD / 64);              // 264 x 11
    k_gemm1_mma<<<g1, 128, G1_BYTES>>>();

    dim3 g2(MTILES, CDIM / 128);             // 264 x 2
    k_gemm2_mma<<<g2, 128, G2_BYTES>>>();

    k_combine<<<(NTOK * (CDIM / 4) + 255) / 256, 256>>>(out);
}

// round 17
// speedup vs baseline: 1.0997x; 1.0225x over previous
#include <cuda_runtime.h>
#include <cuda_fp16.h>
#include <math.h>
#include <stdint.h>

// Problem shapes (fixed)
#define NTOK 16384
#define CDIM 256
#define HDIM 682
#define HPAD 704            // 11 chunks of 64
#define NEXP 8
#define TM   128            // block M tile (slots)
#define BK   64
#define PADDED_MAX (NTOK*2 + NEXP*TM)   // 33792
#define MTILES (PADDED_MAX / TM)        // 264
#define WPELEM (NEXP * HPAD * CDIM)     // 1441792
#define ROUTER_BLOCKS (NTOK / 8)        // 2048
#define PREP_BLOCKS   ((WPELEM / 4 + 255) / 256)  // 1408

// ---------------- device scratch (zero-initialized at load) --------------
__device__ int    d_counts[NEXP];
__device__ int    d_poff[NEXP + 1];
__device__ int    d_cursor[NEXP];
__device__ int    d_slot_token[PADDED_MAX];
__device__ int    d_tok_slot[NTOK * 2];
__device__ float  d_tok_gate[NTOK * 2];
__device__ int    d_tok_expert[NTOK * 2];
__device__ __half d_h[(size_t)PADDED_MAX * HPAD];
__device__ __half d_yvh[(size_t)PADDED_MAX * CDIM];
// fp16 operand copies
__device__ __half d_xc[(size_t)NTOK * CDIM];
__device__ __half d_w1c[WPELEM];   // [E][HPAD][CDIM]
__device__ __half d_w3c[WPELEM];   // [E][HPAD][CDIM]
__device__ __half d_w2c[WPELEM];   // [E][CDIM][HPAD]

// ---------------- helpers ----------------
__device__ __forceinline__ uint32_t smem_u32(const void* p) {
    uint32_t a;
    asm("{ .reg .u64 t; cvta.to.shared.u64 t, %1; cvt.u32.u64 %0, t; }" : "=r"(a) : "l"(p));
    return a;
}
__device__ __forceinline__ void mma_fp16(float c[4], uint32_t a0, uint32_t a1,
                                         uint32_t a2, uint32_t a3,
                                         uint32_t b0, uint32_t b1) {
    asm volatile(
        "mma.sync.aligned.m16n8k16.row.col.f32.f16.f16.f32 "
        "{%0,%1,%2,%3}, {%4,%5,%6,%7}, {%8,%9}, {%0,%1,%2,%3};"
        : "+f"(c[0]), "+f"(c[1]), "+f"(c[2]), "+f"(c[3])
        : "r"(a0), "r"(a1), "r"(a2), "r"(a3), "r"(b0), "r"(b1));
}
__device__ __forceinline__ void ldsm4(uint32_t& r0, uint32_t& r1, uint32_t& r2,
                                      uint32_t& r3, uint32_t addr) {
    asm volatile("ldmatrix.sync.aligned.m8n8.x4.shared.b16 {%0,%1,%2,%3}, [%4];"
                 : "=r"(r0), "=r"(r1), "=r"(r2), "=r"(r3) : "r"(addr));
}
__device__ __forceinline__ void cp16(uint32_t dst, const void* src, uint32_t bytes) {
    asm volatile("cp.async.cg.shared.global [%0], [%1], 16, %2;"
                 :: "r"(dst), "l"(src), "r"(bytes) : "memory");
}
#define CP_COMMIT() asm volatile("cp.async.commit_group;" ::: "memory")
#define CP_WAIT(n)  asm volatile("cp.async.wait_group %0;" :: "n"(n) : "memory")

// SMEM offsets in HALF units, pitch 72 halves (144B), 2 stages
#define PITCH 72
#define G1_A(st)  ((st) * 9216)
#define G1_B1(st) (18432 + (st) * 4608)
#define G1_B3(st) (27648 + (st) * 4608)
#define G1_BYTES  73728
// GEMM2: A 128 rows + B 64 rows per stage
#define G2_A(st)  ((st) * 9216)
#define G2_B(st)  (18432 + (st) * 4608)
#define G2_BYTES  55296

// ------- k_front: merged router (blocks 0..2047) + prep (rest) -----------
__global__ void __launch_bounds__(256) k_front(const float* __restrict__ x,
                                               const float* __restrict__ rw,
                                               const float* __restrict__ w1,
                                               const float* __restrict__ w3,
                                               const float* __restrict__ w2) {
    if (blockIdx.x < ROUTER_BLOCKS) {
        // ---- router (vectorized x path) ----
        __shared__ float s_rw[NEXP * CDIM];
        for (int i = threadIdx.x; i < NEXP * CDIM; i += blockDim.x) s_rw[i] = rw[i];
        __syncthreads();
        int warp = threadIdx.x >> 5, lane = threadIdx.x & 31;
        int n = blockIdx.x * 8 + warp;
        if (n >= NTOK) return;
        const float* xr = x + (size_t)n * CDIM;
        float acc[NEXP];
#pragma unroll
        for (int e = 0; e < NEXP; e++) acc[e] = 0.f;
#pragma unroll
        for (int ch = 0; ch < 2; ch++) {
            int c = ch * 128 + lane * 4;
            float4 v = *(const float4*)&xr[c];
            __half2* dst = (__half2*)&d_xc[(size_t)n * CDIM + c];
            dst[0] = __floats2half2_rn(v.x, v.y);
            dst[1] = __floats2half2_rn(v.z, v.w);
#pragma unroll
            for (int e = 0; e < NEXP; e++) {
                acc[e] = fmaf(v.x, s_rw[e * CDIM + c + 0], acc[e]);
                acc[e] = fmaf(v.y, s_rw[e * CDIM + c + 1], acc[e]);
                acc[e] = fmaf(v.z, s_rw[e * CDIM + c + 2], acc[e]);
                acc[e] = fmaf(v.w, s_rw[e * CDIM + c + 3], acc[e]);
            }
        }
#pragma unroll
        for (int e = 0; e < NEXP; e++)
#pragma unroll
            for (int off = 16; off; off >>= 1)
                acc[e] += __shfl_down_sync(0xffffffffu, acc[e], off);
        if (lane != 0) return;
        float m = acc[0];
#pragma unroll
        for (int e = 1; e < NEXP; e++) m = fmaxf(m, acc[e]);
        float p[NEXP], s = 0.f;
#pragma unroll
        for (int e = 0; e < NEXP; e++) { p[e] = expf(acc[e] - m); s += p[e]; }
        float inv = 1.f / s;
#pragma unroll
        for (int e = 0; e < NEXP; e++) p[e] *= inv;
        int i0 = 0;
#pragma unroll
        for (int e = 1; e < NEXP; e++) if (p[e] > p[i0]) i0 = e;
        int i1 = (i0 == 0) ? 1 : 0;
#pragma unroll
        for (int e = 0; e < NEXP; e++) if (e != i0 && p[e] > p[i1]) i1 = e;
        float denom = p[i0] + p[i1] + 1e-9f;
        d_tok_expert[2 * n + 0] = i0;
        d_tok_expert[2 * n + 1] = i1;
        d_tok_gate[2 * n + 0] = p[i0] / denom;
        d_tok_gate[2 * n + 1] = p[i1] / denom;
        atomicAdd(&d_counts[i0], 1);
        atomicAdd(&d_counts[i1], 1);
    } else {
        // ---- prep: slot init + weight convert/pad (NO d_counts writes) ----
        int i = (blockIdx.x - ROUTER_BLOCKS) * blockDim.x + threadIdx.x;
        if (i < PADDED_MAX) d_slot_token[i] = -1;
        if (i >= WPELEM / 4) return;

        {   // w1/w3 -> half [E][HPAD][CDIM]
            int c4 = i & 63;
            int h  = (i >> 6) % HPAD;
            int e  = i / (64 * HPAD);
            float4 a = make_float4(0.f, 0.f, 0.f, 0.f), b = a;
            if (h < HDIM) {
                size_t off = ((size_t)e * HDIM + h) * CDIM + c4 * 4;
                a = *(const float4*)(w1 + off);
                b = *(const float4*)(w3 + off);
            }
            __half2* p1 = (__half2*)&d_w1c[(size_t)i * 4];
            __half2* p3 = (__half2*)&d_w3c[(size_t)i * 4];
            p1[0] = __floats2half2_rn(a.x, a.y); p1[1] = __floats2half2_rn(a.z, a.w);
            p3[0] = __floats2half2_rn(b.x, b.y); p3[1] = __floats2half2_rn(b.z, b.w);
        }
        {   // w2 -> half [E][CDIM][HPAD]
            int h4 = (i % 176) * 4;
            int c  = (i / 176) % CDIM;
            int e  = i / (176 * CDIM);
            const float* src = w2 + ((size_t)e * CDIM + c) * HDIM + h4;
            float4 v = make_float4(0.f, 0.f, 0.f, 0.f);
            if (h4 + 3 < HDIM) { v.x = src[0]; v.y = src[1]; v.z = src[2]; v.w = src[3]; }
            else {
                if (h4 + 0 < HDIM) v.x = src[0];
                if (h4 + 1 < HDIM) v.y = src[1];
            }
            __half2* p2 = (__half2*)&d_w2c[(size_t)i * 4];
            p2[0] = __floats2half2_rn(v.x, v.y); p2[1] = __floats2half2_rn(v.z, v.w);
        }
    }
}

__global__ void k_setup() {
    if (threadIdx.x == 0) {
        int off = 0;
        for (int e = 0; e < NEXP; e++) {
            d_poff[e] = off;
            d_cursor[e] = off;
            off += ((d_counts[e] + TM - 1) / TM) * TM;
            d_counts[e] = 0;
        }
        d_poff[NEXP] = off;
    }
}

// warp-aggregated scatter: one atomicAdd per (warp, expert) via match_any
__global__ void k_scatter() {
    int i = blockIdx.x * blockDim.x + threadIdx.x;   // grid covers exactly NTOK*2
    int lane = threadIdx.x & 31;
    int n = i >> 1;
    int e = d_tok_expert[i];
    unsigned mask = __match_any_sync(0xffffffffu, e);
    int leader = __ffs(mask) - 1;
    int rank = __popc(mask & ((1u << lane) - 1));
    int base = 0;
    if (lane == leader) base = atomicAdd(&d_cursor[e], __popc(mask));
    base = __shfl_sync(0xffffffffu, base, leader);
    int pos = base + rank;
    d_slot_token[pos] = n;
    d_tok_slot[i] = pos;
}

// ---------------- GEMM1: h = silu(x w1^T) * (x w3^T) ---------------------
// 128 thr = 4 warps (2M x 2N), warp tile 64x32, block 128x64, BK=64,
// 2-stage, ldmatrix fragments, minctasm=3.
__global__ void __launch_bounds__(128, 3) k_gemm1_mma() {
    extern __shared__ __half smh[];
    __shared__ int s_tok[TM];
    uint32_t sb = smem_u32(smh);

    int sbase = blockIdx.x * TM;
    if (sbase >= d_poff[NEXP]) return;
    int e = 0;
#pragma unroll
    for (int q = 0; q < NEXP - 1; q++) if (d_poff[q + 1] <= sbase) e = q + 1;
    int n0 = blockIdx.y * 64;

    int tid = threadIdx.x, lane = tid & 31, wid = tid >> 5;
    int wm = wid >> 1, wn = wid & 1;
    s_tok[tid] = d_slot_token[sbase + tid];
    __syncthreads();

    const __half* w1e = d_w1c + (size_t)e * HPAD * CDIM;
    const __half* w3e = d_w3c + (size_t)e * HPAD * CDIM;

    auto load_chunk = [&](int c, int st) {
        int k0 = c * BK;
#pragma unroll
        for (int t = 0; t < 8; t++) {                    // A: 1024 x 16B
            int i = tid + t * 128;
            int m = i >> 3, f4 = i & 7;
            int tok = s_tok[m];
            const __half* src = (tok >= 0) ? &d_xc[(size_t)tok * CDIM + k0 + f4 * 8] : d_xc;
            cp16(sb + (G1_A(st) + m * PITCH + f4 * 8) * 2, src, (tok >= 0) ? 16u : 0u);
        }
#pragma unroll
        for (int t = 0; t < 4; t++) {                    // B1/B3: 512 x 16B each
            int i = tid + t * 128;
            int nn = i >> 3, f4 = i & 7;
            size_t off = (size_t)(n0 + nn) * CDIM + k0 + f4 * 8;
            cp16(sb + (G1_B1(st) + nn * PITCH + f4 * 8) * 2, w1e + off, 16u);
            cp16(sb + (G1_B3(st) + nn * PITCH + f4 * 8) * 2, w3e + off, 16u);
        }
    };

    float c1[4][4][4], c3[4][4][4];
#pragma unroll
    for (int mt = 0; mt < 4; mt++)
#pragma unroll
        for (int nt = 0; nt < 4; nt++)
#pragma unroll
            for (int r = 0; r < 4; r++) { c1[mt][nt][r] = 0.f; c3[mt][nt][r] = 0.f; }

    int lr = lane >> 2, lc = lane & 3;
    int arow = (lane & 7) + ((lane >> 3) & 1) * 8;
    int akof = ((lane >> 4) & 1) * 8;
    int brow = ((lane >> 4) & 1) * 8 + (lane & 7);
    int bkof = ((lane >> 3) & 1) * 8;
    const int NC = CDIM / BK;   // 4

    load_chunk(0, 0);
    CP_COMMIT();

    for (int c = 0; c < NC; c++) {
        int st = c & 1;
        if (c + 1 < NC) { load_chunk(c + 1, st ^ 1); CP_COMMIT(); CP_WAIT(1); }
        else            { CP_WAIT(0); }
        __syncthreads();

#pragma unroll
        for (int ks = 0; ks < BK / 16; ks++) {
            int k = ks * 16;
            uint32_t a[4][4], b1r[4][2], b3r[4][2];
#pragma unroll
            for (int mt = 0; mt < 4; mt++) {
                int row = wm * 64 + mt * 16 + arow;
                ldsm4(a[mt][0], a[mt][1], a[mt][2], a[mt][3],
                      sb + (G1_A(st) + row * PITCH + k + akof) * 2);
            }
#pragma unroll
            for (int p = 0; p < 2; p++) {
                int col = wn * 32 + p * 16 + brow;
                ldsm4(b1r[p*2][0], b1r[p*2][1], b1r[p*2+1][0], b1r[p*2+1][1],
                      sb + (G1_B1(st) + col * PITCH + k + bkof) * 2);
                ldsm4(b3r[p*2][0], b3r[p*2][1], b3r[p*2+1][0], b3r[p*2+1][1],
                      sb + (G1_B3(st) + col * PITCH + k + bkof) * 2);
            }
#pragma unroll
            for (int nt = 0; nt < 4; nt++)
#pragma unroll
                for (int mt = 0; mt < 4; mt++) {
                    mma_fp16(c1[mt][nt], a[mt][0], a[mt][1], a[mt][2], a[mt][3],
                             b1r[nt][0], b1r[nt][1]);
                    mma_fp16(c3[mt][nt], a[mt][0], a[mt][1], a[mt][2], a[mt][3],
                             b3r[nt][0], b3r[nt][1]);
                }
        }
        __syncthreads();
    }

    // epilogue: h = silu(c1)*c3 -> half
#pragma unroll
    for (int mt = 0; mt < 4; mt++) {
#pragma unroll
        for (int nt = 0; nt < 4; nt++) {
#pragma unroll
            for (int half = 0; half < 2; half++) {
                int row = sbase + wm * 64 + mt * 16 + lr + half * 8;
                int col = n0 + wn * 32 + nt * 8 + lc * 2;
                float a0 = c1[mt][nt][half * 2 + 0], a1 = c1[mt][nt][half * 2 + 1];
                float b0 = c3[mt][nt][half * 2 + 0], b1 = c3[mt][nt][half * 2 + 1];
                float h0 = a0 / (1.f + expf(-a0)) * b0;
                float h1 = a1 / (1.f + expf(-a1)) * b1;
                *(__half2*)&d_h[(size_t)row * HPAD + col] = __floats2half2_rn(h0, h1);
            }
        }
    }
}

// ---------------- GEMM2: y = h w2^T (fp16 output) ------------------------
// 128 thr = 4 warps (2M x 2N), warp tile 64x32, block 128x64, BK=64,
// 2-stage, ldmatrix, minctasm=4 (55 KB smem, ~120 regs).
__global__ void __launch_bounds__(128, 4) k_gemm2_mma() {
    extern __shared__ __half smh[];
    uint32_t sb = smem_u32(smh);

    int sbase = blockIdx.x * TM;
    if (sbase >= d_poff[NEXP]) return;
    int e = 0;
#pragma unroll
    for (int q = 0; q < NEXP - 1; q++) if (d_poff[q + 1] <= sbase) e = q + 1;
    int n0 = blockIdx.y * 64;

    int tid = threadIdx.x, lane = tid & 31, wid = tid >> 5;
    int wm = wid >> 1, wn = wid & 1;
    const __half* w2e = d_w2c + (size_t)e * CDIM * HPAD;

    auto load_chunk = [&](int c, int st) {
        int k0 = c * BK;
#pragma unroll
        for (int t = 0; t < 8; t++) {                    // A (d_h): 1024 x 16B
            int i = tid + t * 128;
            int m = i >> 3, f4 = i & 7;
            cp16(sb + (G2_A(st) + m * PITCH + f4 * 8) * 2,
                 &d_h[(size_t)(sbase + m) * HPAD + k0 + f4 * 8], 16u);
        }
#pragma unroll
        for (int t = 0; t < 4; t++) {                    // B (w2c): 512 x 16B
            int i = tid + t * 128;
            int nn = i >> 3, f4 = i & 7;
            cp16(sb + (G2_B(st) + nn * PITCH + f4 * 8) * 2,
                 &w2e[(size_t)(n0 + nn) * HPAD + k0 + f4 * 8], 16u);
        }
    };

    float cacc[4][4][4];
#pragma unroll
    for (int mt = 0; mt < 4; mt++)
#pragma unroll
        for (int nt = 0; nt < 4; nt++)
#pragma unroll
            for (int r = 0; r < 4; r++) cacc[mt][nt][r] = 0.f;

    int lr = lane >> 2, lc = lane & 3;
    int arow = (lane & 7) + ((lane >> 3) & 1) * 8;
    int akof = ((lane >> 4) & 1) * 8;
    int brow = ((lane >> 4) & 1) * 8 + (lane & 7);
    int bkof = ((lane >> 3) & 1) * 8;
    const int NC = HPAD / BK;   // 11

    load_chunk(0, 0);
    CP_COMMIT();

    for (int c = 0; c < NC; c++) {
        int st = c & 1;
        if (c + 1 < NC) { load_chunk(c + 1, st ^ 1); CP_COMMIT(); CP_WAIT(1); }
        else            { CP_WAIT(0); }
        __syncthreads();

#pragma unroll
        for (int ks = 0; ks < BK / 16; ks++) {
            int k = ks * 16;
            uint32_t a[4][4], br[4][2];
#pragma unroll
            for (int mt = 0; mt < 4; mt++) {
                int row = wm * 64 + mt * 16 + arow;
                ldsm4(a[mt][0], a[mt][1], a[mt][2], a[mt][3],
                      sb + (G2_A(st) + row * PITCH + k + akof) * 2);
            }
#pragma unroll
            for (int p = 0; p < 2; p++) {
                int col = wn * 32 + p * 16 + brow;
                ldsm4(br[p*2][0], br[p*2][1], br[p*2+1][0], br[p*2+1][1],
                      sb + (G2_B(st) + col * PITCH + k + bkof) * 2);
            }
#pragma unroll
            for (int nt = 0; nt < 4; nt++)
#pragma unroll
                for (int mt = 0; mt < 4; mt++)
                    mma_fp16(cacc[mt][nt], a[mt][0], a[mt][1], a[mt][2], a[mt][3],
                             br[nt][0], br[nt][1]);
        }
        __syncthreads();
    }

#pragma unroll
    for (int mt = 0; mt < 4; mt++) {
#pragma unroll
        for (int nt = 0; nt < 4; nt++) {
#pragma unroll
            for (int half = 0; half < 2; half++) {
                int row = sbase + wm * 64 + mt * 16 + lr + half * 8;
                int col = n0 + wn * 32 + nt * 8 + lc * 2;
                *(__half2*)&d_yvh[(size_t)row * CDIM + col] =
                    __floats2half2_rn(cacc[mt][nt][half * 2 + 0],
                                      cacc[mt][nt][half * 2 + 1]);
            }
        }
    }
}

// ---------------- combine (16B loads of fp16 y) ----------------
__global__ void k_combine(float* __restrict__ out) {
    int idx = blockIdx.x * blockDim.x + threadIdx.x;   // NTOK * (CDIM/8)
    if (idx >= NTOK * (CDIM / 8)) return;
    int n = idx >> 5, c8 = (idx & 31) * 8;
    int s0 = d_tok_slot[2 * n + 0], s1 = d_tok_slot[2 * n + 1];
    float g0 = d_tok_gate[2 * n + 0], g1 = d_tok_gate[2 * n + 1];
    uint4 r0 = *(const uint4*)&d_yvh[(size_t)s0 * CDIM + c8];
    uint4 r1 = *(const uint4*)&d_yvh[(size_t)s1 * CDIM + c8];
    const __half2* h0 = (const __half2*)&r0;
    const __half2* h1 = (const __half2*)&r1;
    float* op = &out[(size_t)n * CDIM + c8];
    float4 o0, o1;
    float2 a, b;
    a = __half22float2(h0[0]); b = __half22float2(h1[0]);
    o0.x = g0 * a.x + g1 * b.x; o0.y = g0 * a.y + g1 * b.y;
    a = __half22float2(h0[1]); b = __half22float2(h1[1]);
    o0.z = g0 * a.x + g1 * b.x; o0.w = g0 * a.y + g1 * b.y;
    a = __half22float2(h0[2]); b = __half22float2(h1[2]);
    o1.x = g0 * a.x + g1 * b.x; o1.y = g0 * a.y + g1 * b.y;
    a = __half22float2(h0[3]); b = __half22float2(h1[3]);
    o1.z = g0 * a.x + g1 * b.x; o1.w = g0 * a.y + g1 * b.y;
    *(float4*)op = o0;
    *(float4*)(op + 4) = o1;
}

// ---------------- launch ----------------
extern "C" void kernel_launch(void* const* d_in, const int* in_sizes, int n_in,
                              void* d_out, int out_size) {
    const float* x  = (const float*)d_in[0];
    const float* rw = (const float*)d_in[1];
    const float* w1 = (const float*)d_in[2];
    const float* w2 = (const float*)d_in[3];
    const float* w3 = (const float*)d_in[4];
    float* out = (float*)d_out;

    cudaFuncSetAttribute(k_gemm1_mma, cudaFuncAttributeMaxDynamicSharedMemorySize, G1_BYTES);
    cudaFuncSetAttribute(k_gemm2_mma, cudaFuncAttributeMaxDynamicSharedMemorySize, G2_BYTES);

    k_front<<<ROUTER_BLOCKS + PREP_BLOCKS, 256>>>(x, rw, w1, w3, w2);
    k_setup<<<1, 32>>>();
    k_scatter<<<(NTOK * 2) / 256, 256>>>();

    dim3 g1(MTILES, HPAD / 64);              // 264 x 11
    k_gemm1_mma<<<g1, 128, G1_BYTES>>>();

    dim3 g2(MTILES, CDIM / 64);              // 264 x 4
    k_gemm2_mma<<<g2, 128, G2_BYTES>>>();

    k_combine<<<(NTOK * (CDIM / 8) + 255) / 256, 256>>>(out);
}